// round 13
// baseline (speedup 1.0000x reference)
#include <cuda_runtime.h>
#include <cuda_fp16.h>
#include <cstdint>
#include <math.h>

#define Bb 8
#define SS 2048
#define DD 1024
#define HH 16
#define DHH 64
#define MM (Bb * SS)
#define SCALE 0.125f
#define NCH 16              // S-chunks for pooling kernels
#define CHS (SS / NCH)      // 128

// ---------------- helpers ---------------------------------------------------
__device__ __forceinline__ uint32_t smem_to_u32(const void* p) {
    uint32_t a;
    asm("{ .reg .u64 t; cvta.to.shared.u64 t, %1; cvt.u32.u64 %0, t; }"
        : "=r"(a) : "l"(p));
    return a;
}
__device__ __forceinline__ void ldsm_x4(uint32_t* r, uint32_t addr) {
    asm volatile("ldmatrix.sync.aligned.m8n8.x4.shared.b16 {%0,%1,%2,%3}, [%4];"
        : "=r"(r[0]), "=r"(r[1]), "=r"(r[2]), "=r"(r[3]) : "r"(addr));
}
__device__ __forceinline__ void mma16816(float* c, const uint32_t* a,
                                         uint32_t b0, uint32_t b1) {
    asm volatile("mma.sync.aligned.m16n8k16.row.col.f32.f16.f16.f32 "
        "{%0,%1,%2,%3}, {%4,%5,%6,%7}, {%8,%9}, {%0,%1,%2,%3};"
        : "+f"(c[0]), "+f"(c[1]), "+f"(c[2]), "+f"(c[3])
        : "r"(a[0]), "r"(a[1]), "r"(a[2]), "r"(a[3]), "r"(b0), "r"(b1));
}
__device__ __forceinline__ void cp_async16(uint32_t saddr, const void* gaddr) {
    asm volatile("cp.async.cg.shared.global [%0], [%1], 16;"
        :: "r"(saddr), "l"(gaddr));
}
#define CP_COMMIT() asm volatile("cp.async.commit_group;" ::: "memory")
#define CP_WAIT_1() asm volatile("cp.async.wait_group 1;" ::: "memory")
#define CP_WAIT_0() asm volatile("cp.async.wait_group 0;" ::: "memory")

// ---------------- scratch (device globals) ---------------------------------
__device__ float g_qlt[Bb * HH * SS];           // q logits, [bh][s]
__device__ float g_qkl[Bb * HH * SS];           // qk logits, [bh][s]
__device__ float g_ypart[(size_t)Bb * NCH * HH * DD];  // pooled-hs partials
__device__ float g_mstat[Bb * HH * NCH * 2];    // per-chunk (max, expsum)
__device__ float g_pq[Bb * HH * DHH];
__device__ float g_pk[Bb * HH * DHH];
__device__ float g_wql[DD * HH];                // Wq@Wqa (fp32)
__device__ float g_cql[HH];                     // bq@Wqa + bqa
__device__ float g_u[Bb * HH * DD];             // Wk[:,hsl]@pq per bh
__device__ float g_cv[Bb * HH];                 // bk[hsl].pq per bh
__device__ __half g_hsh[(size_t)MM * DD];
__device__ __half g_qh[(size_t)MM * DD];        // fp16 q (GEMM1 output)
__device__ __half g_wq[DD * DD];
__device__ __half g_wk[DD * DD];
__device__ __half g_wt[DD * DD];
__device__ __half g_wtb[(size_t)Bb * DD * DD];  // per-batch pk-scaled Wt^T

// ---------------- conversion: fp32 -> fp16 ----------------------------------
__global__ void __launch_bounds__(256)
conv_half(const float* __restrict__ X, __half* __restrict__ out)
{
    size_t e = (size_t)blockIdx.x * 256 + threadIdx.x;  // float4 index
    float4 v = ((const float4*)X)[e];
    __half hv[4];
    hv[0] = __float2half_rn(v.x); hv[1] = __float2half_rn(v.y);
    hv[2] = __float2half_rn(v.z); hv[3] = __float2half_rn(v.w);
    ((uint2*)out)[e] = *(uint2*)hv;
}

// ---------------- conversion: weight transpose to fp16 ---------------------
__global__ void __launch_bounds__(256)
conv_w(const float* __restrict__ W, __half* __restrict__ wt)
{
    __shared__ float s[32][33];
    int n0 = blockIdx.x * 32, k0 = blockIdx.y * 32;
    int tx = threadIdx.x & 31, ty = threadIdx.x >> 5;  // 32 x 8
#pragma unroll
    for (int i = 0; i < 4; i++) {
        int r = ty + i * 8;
        s[r][tx] = W[(size_t)(k0 + r) * DD + n0 + tx];
    }
    __syncthreads();
#pragma unroll
    for (int i = 0; i < 4; i++) {
        int r = ty + i * 8;
        wt[(size_t)(n0 + r) * DD + k0 + tx] = __float2half_rn(s[tx][r]);
    }
}

// ---------------- Wql = Wq @ Wqa  (fp32), cql = bq@Wqa + bqa ---------------
// grid 64 blocks x 256 thr; block handles 16 k-rows; smem = Wqa^T (64 KB)
__global__ void __launch_bounds__(256)
wql_kernel(const float* __restrict__ Wq, const float* __restrict__ Wqa,
           const float* __restrict__ bq, const float* __restrict__ bqa,
           float* __restrict__ wql, float* __restrict__ cql)
{
    extern __shared__ float sW[];   // [HH][DD]
    int t = threadIdx.x;
    for (int i = t; i < DD * HH; i += 256) {
        int n = i >> 4, h = i & 15;
        sW[h * DD + n] = Wqa[i];
    }
    __syncthreads();
    int warp = t >> 5, lane = t & 31;
#pragma unroll
    for (int r = 0; r < 2; r++) {
        int k = blockIdx.x * 16 + warp * 2 + r;
        const float* wr = Wq + (size_t)k * DD;
        float acc[HH];
#pragma unroll
        for (int h = 0; h < HH; h++) acc[h] = 0.0f;
#pragma unroll
        for (int j = 0; j < 8; j++) {
            float4 v = *(const float4*)(wr + lane * 4 + 128 * j);
#pragma unroll
            for (int h = 0; h < HH; h++) {
                float4 u4 = *(const float4*)(sW + h * DD + lane * 4 + 128 * j);
                acc[h] += v.x * u4.x + v.y * u4.y + v.z * u4.z + v.w * u4.w;
            }
        }
#pragma unroll
        for (int h = 0; h < HH; h++) {
#pragma unroll
            for (int off = 16; off; off >>= 1)
                acc[h] += __shfl_xor_sync(0xffffffffu, acc[h], off);
            if (lane == 0) wql[k * HH + h] = acc[h];
        }
    }
    if (blockIdx.x == 0 && t < HH) {
        float a = 0.0f;
        for (int n = 0; n < DD; n++) a += bq[n] * Wqa[n * HH + t];
        cql[t] = a + bqa[t];
    }
}

// ---------------- logits: lt[bh][s] = X[m,:] . Wmat[:,h] + bias[h] ---------
// Wmat layout [k][h] (k-major, h fastest) like Wqa. X = hs. 512 blocks.
__global__ void __launch_bounds__(256)
qlogits_kernel(const float* __restrict__ Wmat, const float* __restrict__ bias,
               const float* __restrict__ X, float* __restrict__ lt)
{
    extern __shared__ float sW[];   // [HH][DD] transposed, 64 KB
    int tid = threadIdx.x;
    for (int i = tid; i < DD * HH; i += 256) {
        int k = i >> 4, h = i & 15;
        sW[h * DD + k] = Wmat[i];
    }
    __syncthreads();

    int warp = tid >> 5, lane = tid & 31;
    for (int rr = 0; rr < 4; rr++) {
        int m = blockIdx.x * 32 + warp * 4 + rr;
        const float* xrow = X + (size_t)m * DD;
        float acc[HH];
#pragma unroll
        for (int h = 0; h < HH; h++) acc[h] = 0.0f;
        for (int k = lane; k < DD; k += 32) {
            float qv = xrow[k];
#pragma unroll
            for (int h = 0; h < HH; h++) acc[h] += qv * sW[h * DD + k];
        }
#pragma unroll
        for (int h = 0; h < HH; h++)
#pragma unroll
            for (int off = 16; off; off >>= 1)
                acc[h] += __shfl_xor_sync(0xffffffffu, acc[h], off);
        if (lane == 0) {
            int b = m >> 11, s = m & (SS - 1);
#pragma unroll
            for (int h = 0; h < HH; h++)
                lt[((size_t)(b * HH + h)) * SS + s] = acc[h] + bias[h];
        }
    }
}

// ---------------- pooled-hs partial, h-fused, local softmax stats ----------
// grid (NCH, Bb), 256 thr. ypart[((b*NCH+ch)*HH+h)*DD + d] unnormalized.
__global__ void __launch_bounds__(256)
poolpart_kernel(const float* __restrict__ lt, const float* __restrict__ mask,
                const float* __restrict__ hs, float* __restrict__ ypart,
                float* __restrict__ mstat)
{
    __shared__ float wsm[HH][CHS];      // 8 KB
    int ch = blockIdx.x, b = blockIdx.y;
    int t = threadIdx.x, warp = t >> 5, lane = t & 31;
    int s0 = ch * CHS;

#pragma unroll
    for (int hh = 0; hh < 2; hh++) {
        int h = warp * 2 + hh;
        float lv[4];
        float mx = -1e30f;
#pragma unroll
        for (int j = 0; j < 4; j++) {
            int sl = lane + 32 * j;
            lv[j] = lt[((size_t)(b * HH + h)) * SS + s0 + sl] * SCALE +
                    mask[(size_t)b * SS + s0 + sl];
            mx = fmaxf(mx, lv[j]);
        }
#pragma unroll
        for (int off = 16; off; off >>= 1)
            mx = fmaxf(mx, __shfl_xor_sync(0xffffffffu, mx, off));
        float es = 0.0f;
#pragma unroll
        for (int j = 0; j < 4; j++) {
            float e = __expf(lv[j] - mx);
            wsm[h][lane + 32 * j] = e;
            es += e;
        }
#pragma unroll
        for (int off = 16; off; off >>= 1)
            es += __shfl_xor_sync(0xffffffffu, es, off);
        if (lane == 0) {
            mstat[((size_t)(b * HH + h) * NCH + ch) * 2]     = mx;
            mstat[((size_t)(b * HH + h) * NCH + ch) * 2 + 1] = es;
        }
    }
    __syncthreads();

    // weighted sums of hs rows: thread owns 4 d-columns
    float acc[HH][4];
#pragma unroll
    for (int h = 0; h < HH; h++)
#pragma unroll
        for (int j = 0; j < 4; j++) acc[h][j] = 0.0f;

    const float* hsb = hs + ((size_t)(b * SS + s0)) * DD + t * 4;
    for (int s = 0; s < CHS; s++) {
        float4 v = *(const float4*)(hsb + (size_t)s * DD);
#pragma unroll
        for (int h = 0; h < HH; h++) {
            float wv = wsm[h][s];
            acc[h][0] += wv * v.x; acc[h][1] += wv * v.y;
            acc[h][2] += wv * v.z; acc[h][3] += wv * v.w;
        }
    }
#pragma unroll
    for (int h = 0; h < HH; h++)
        *(float4*)&ypart[(((size_t)b * NCH + ch) * HH + h) * DD + t * 4] =
            *(float4*)acc[h];
}

// ---------------- reduce partials + project through fp16 W^T ---------------
// grid (Bb*HH), 256 thr. out[bh][dh] = (y @ W[:,h*64+dh]) + bias[h*64+dh]
__global__ void __launch_bounds__(256)
poolproj_kernel(const float* __restrict__ ypart, const float* __restrict__ mstat,
                const __half* __restrict__ wT, const float* __restrict__ bias,
                float* __restrict__ outp)
{
    __shared__ float y[DD];
    int bh = blockIdx.x, b = bh >> 4, h = bh & 15;
    int t = threadIdx.x, warp = t >> 5, lane = t & 31;

    float ml[NCH], es[NCH];
    float gmax = -1e30f;
#pragma unroll
    for (int c = 0; c < NCH; c++) {
        ml[c] = mstat[((size_t)bh * NCH + c) * 2];
        es[c] = mstat[((size_t)bh * NCH + c) * 2 + 1];
        gmax = fmaxf(gmax, ml[c]);
    }
    float denom = 0.0f;
    float f[NCH];
#pragma unroll
    for (int c = 0; c < NCH; c++) {
        f[c] = __expf(ml[c] - gmax);
        denom += es[c] * f[c];
    }
    float inv = 1.0f / denom;
#pragma unroll
    for (int r = 0; r < 4; r++) {
        int d = t + 256 * r;
        float a = 0.0f;
#pragma unroll
        for (int c = 0; c < NCH; c++)
            a += ypart[(((size_t)b * NCH + c) * HH + h) * DD + d] * f[c];
        y[d] = a * inv;
    }
    __syncthreads();

    // projection: 8 warps x 8 outputs
#pragma unroll
    for (int o = 0; o < 8; o++) {
        int col = h * DHH + warp * 8 + o;
        const __half* wr = wT + (size_t)col * DD;
        float a = 0.0f;
#pragma unroll
        for (int j = 0; j < 16; j++) {
            __half2 hv = *(const __half2*)(wr + lane * 2 + 64 * j);
            float2 fv = __half22float2(hv);
            a += y[lane * 2 + 64 * j] * fv.x + y[lane * 2 + 64 * j + 1] * fv.y;
        }
#pragma unroll
        for (int off = 16; off; off >>= 1)
            a += __shfl_xor_sync(0xffffffffu, a, off);
        if (lane == 0)
            outp[(size_t)bh * DHH + warp * 8 + o] = a + bias[col];
    }
}

// ---------------- u[bh][k] = Wk[k, hsl].pq[bh],  cv[bh] = bk[hsl].pq -------
__global__ void __launch_bounds__(256)
uvec_kernel(const float* __restrict__ Wk, const float* __restrict__ bk,
            const float* __restrict__ pq, float* __restrict__ u,
            float* __restrict__ cv)
{
    __shared__ float spq[DHH];
    __shared__ float red[DHH];
    int bh = blockIdx.x, h = bh & 15;
    int t = threadIdx.x;
    if (t < DHH) spq[t] = pq[(size_t)bh * DHH + t];
    __syncthreads();
#pragma unroll
    for (int r = 0; r < 4; r++) {
        int k = t + 256 * r;
        const float* wr = Wk + (size_t)k * DD + h * DHH;
        float a = 0.0f;
#pragma unroll
        for (int j = 0; j < DHH; j++) a += wr[j] * spq[j];
        u[(size_t)bh * DD + k] = a;
    }
    if (t < DHH) red[t] = bk[h * DHH + t] * spq[t];
    __syncthreads();
    if (t == 0) {
        float s = 0.0f;
        for (int j = 0; j < DHH; j++) s += red[j];
        cv[bh] = s;
    }
}

// ---------------- qk logits, h-fused: qkl[bh][s] = hs[b,s].u[bh] + cv ------
// grid (NCH, Bb), 256 thr, dyn smem = 64 KB (u rows for this b)
__global__ void __launch_bounds__(256)
qklogits_kernel(const float* __restrict__ hs, const float* __restrict__ u,
                const float* __restrict__ cv, float* __restrict__ qkl)
{
    extern __shared__ float su[];   // [HH][DD]
    __shared__ float sc[HH];
    int ch = blockIdx.x, b = blockIdx.y;
    int t = threadIdx.x, warp = t >> 5, lane = t & 31;
    for (int i = t; i < HH * DD; i += 256) su[i] = u[(size_t)b * HH * DD + i];
    if (t < HH) sc[t] = cv[b * HH + t];
    __syncthreads();

#pragma unroll
    for (int i = 0; i < CHS / 8; i++) {
        int sl = warp + 8 * i;
        int s = ch * CHS + sl;
        const float* hr = hs + ((size_t)(b * SS + s)) * DD;
        float acc[HH];
#pragma unroll
        for (int h = 0; h < HH; h++) acc[h] = 0.0f;
#pragma unroll
        for (int j = 0; j < 8; j++) {
            float4 v = *(const float4*)(hr + lane * 4 + 128 * j);
#pragma unroll
            for (int h = 0; h < HH; h++) {
                float4 u4 = *(const float4*)(su + h * DD + lane * 4 + 128 * j);
                acc[h] += v.x * u4.x + v.y * u4.y + v.z * u4.z + v.w * u4.w;
            }
        }
#pragma unroll
        for (int h = 0; h < HH; h++) {
#pragma unroll
            for (int off = 16; off; off >>= 1)
                acc[h] += __shfl_xor_sync(0xffffffffu, acc[h], off);
            if (lane == 0)
                qkl[((size_t)(b * HH + h)) * SS + s] = acc[h] + sc[h];
        }
    }
}

// ---------------- per-batch scaled weight: W'_b[n][k] = wt[n][k]*pk[b][k] --
__global__ void __launch_bounds__(256)
scale_wt_kernel(const __half* __restrict__ wt, const float* __restrict__ pk,
                __half* __restrict__ wtb)
{
    int b = blockIdx.y;
    size_t e = (size_t)blockIdx.x * 1024 + threadIdx.x * 4;  // half index
    int kk = (int)(e & (DD - 1));
    uint2 raw = *(const uint2*)(wt + e);
    __half* hv = (__half*)&raw;
    float4 p = *(const float4*)(pk + (size_t)b * DD + kk);
    __half ov[4];
    ov[0] = __float2half_rn(__half2float(hv[0]) * p.x);
    ov[1] = __float2half_rn(__half2float(hv[1]) * p.y);
    ov[2] = __float2half_rn(__half2float(hv[2]) * p.z);
    ov[3] = __float2half_rn(__half2float(hv[3]) * p.w);
    *(uint2*)(wtb + (size_t)b * DD * DD + e) = *(uint2*)ov;
}

// ---------------- HMMA GEMM ------------------------------------------------
// MODE 0: Ch = fp16(A@B^T + bias)            (q projection)
// MODE 1: C  = A@B^T + bias + residH (fp16)  (final transform, B per-batch)
constexpr int PITCH = 80;
constexpr int TILEB = 128 * PITCH;         // 10240
constexpr int STAGEB = 2 * TILEB;          // 20480
constexpr int SMEMB = 3 * STAGEB;          // 61440
constexpr int NKT = 32;

template <int MODE>
__global__ void __launch_bounds__(256, 2)
gemm_tc(const __half* __restrict__ Ah, const __half* __restrict__ Bw,
        const float* __restrict__ bias, const __half* __restrict__ residH,
        float* __restrict__ C, __half* __restrict__ Ch, int bStrideBatch)
{
    extern __shared__ char smem[];
    const uint32_t sb = smem_to_u32(smem);
    const int tid = threadIdx.x, wid = tid >> 5, lane = tid & 31;
    const int warp_m = wid & 3, warp_n = wid >> 2;
    const int n0 = blockIdx.x * 128;
    const int m0 = blockIdx.y * 128;
    if (MODE == 1) Bw += (size_t)(m0 >> 11) * bStrideBatch;

    float acc[2][8][4];
#pragma unroll
    for (int i = 0; i < 2; i++)
#pragma unroll
        for (int j = 0; j < 8; j++)
#pragma unroll
            for (int l = 0; l < 4; l++) acc[i][j][l] = 0.0f;

    auto load_stage = [&](int kt, int st) {
        const int k0 = kt * 32;
#pragma unroll
        for (int tile = 0; tile < 2; tile++) {
            const int rowoff = (tile == 0) ? m0 : n0;
            const __half* base = (tile == 0) ? Ah : Bw;
#pragma unroll
            for (int h = 0; h < 2; h++) {
                int c = tid + h * 256;
                int row = c >> 2, cc = c & 3;
                uint32_t sa = sb + st * STAGEB + tile * TILEB + row * PITCH + cc * 16;
                cp_async16(sa, base + (size_t)(rowoff + row) * DD + k0 + cc * 8);
            }
        }
    };

    load_stage(0, 0); CP_COMMIT();
    load_stage(1, 1); CP_COMMIT();

    for (int kt = 0; kt < NKT; kt++) {
        if (kt == NKT - 1) { CP_WAIT_0(); } else { CP_WAIT_1(); }
        __syncthreads();
        if (kt + 2 < NKT) {
            load_stage(kt + 2, (kt + 2) % 3);
            CP_COMMIT();
        }

        const uint32_t s0 = sb + (kt % 3) * STAGEB;
        const int rsel = lane & 15;
        const int hsel = (lane >> 4) * 16;

#pragma unroll
        for (int kp = 0; kp < 2; kp++) {
            uint32_t ah[2][4];
            const int ksel = hsel + kp * 32;
#pragma unroll
            for (int mi = 0; mi < 2; mi++) {
                uint32_t off = (uint32_t)(warp_m * 32 + mi * 16 + rsel) * PITCH + ksel;
                ldsm_x4(ah[mi], s0 + off);
            }
#pragma unroll
            for (int np = 0; np < 4; np++) {
                uint32_t off = (uint32_t)(warp_n * 64 + np * 16 + rsel) * PITCH + ksel;
                uint32_t bh[4];
                ldsm_x4(bh, s0 + TILEB + off);
#pragma unroll
                for (int mi = 0; mi < 2; mi++) {
                    mma16816(acc[mi][2 * np],     ah[mi], bh[0], bh[2]);
                    mma16816(acc[mi][2 * np + 1], ah[mi], bh[1], bh[3]);
                }
            }
        }
    }

    // ---------------- epilogue ----------------
#pragma unroll
    for (int mi = 0; mi < 2; mi++) {
        int row = m0 + warp_m * 32 + mi * 16 + (lane >> 2);
#pragma unroll
        for (int ni = 0; ni < 8; ni++) {
            int col = n0 + warp_n * 64 + ni * 8 + (lane & 3) * 2;
            float b0 = __ldg(bias + col), b1 = __ldg(bias + col + 1);
            float2 v0, v1;
            v0.x = acc[mi][ni][0] + b0;  v0.y = acc[mi][ni][1] + b1;
            v1.x = acc[mi][ni][2] + b0;  v1.y = acc[mi][ni][3] + b1;
            if (MODE == 0) {
                *(__half2*)(Ch + (size_t)row * DD + col) =
                    __floats2half2_rn(v0.x, v0.y);
                *(__half2*)(Ch + (size_t)(row + 8) * DD + col) =
                    __floats2half2_rn(v1.x, v1.y);
            } else {
                float2 r0 = __half22float2(*(const __half2*)(residH + (size_t)row * DD + col));
                float2 r1 = __half22float2(*(const __half2*)(residH + (size_t)(row + 8) * DD + col));
                v0.x += r0.x; v0.y += r0.y; v1.x += r1.x; v1.y += r1.y;
                *(float2*)(C + (size_t)row * DD + col) = v0;
                *(float2*)(C + (size_t)(row + 8) * DD + col) = v1;
            }
        }
    }
}

// ---------------------------------------------------------------------------
extern "C" void kernel_launch(void* const* d_in, const int* in_sizes, int n_in,
                              void* d_out, int out_size)
{
    const float* hs   = (const float*)d_in[0];
    const float* mask = (const float*)d_in[1];
    const float* Wq   = (const float*)d_in[2];
    const float* bq   = (const float*)d_in[3];
    const float* Wqa  = (const float*)d_in[4];
    const float* bqa  = (const float*)d_in[5];
    const float* Wk   = (const float*)d_in[6];
    const float* bk   = (const float*)d_in[7];
    const float* Wt   = (const float*)d_in[8];
    const float* bt   = (const float*)d_in[9];
    float* out = (float*)d_out;

    float *qlt, *qkl, *ypart, *mstat, *pq, *pk, *wql, *cql, *u, *cv;
    __half *hsh, *qh, *wq, *wk, *wt, *wtb;
    cudaGetSymbolAddress((void**)&qlt, g_qlt);
    cudaGetSymbolAddress((void**)&qkl, g_qkl);
    cudaGetSymbolAddress((void**)&ypart, g_ypart);
    cudaGetSymbolAddress((void**)&mstat, g_mstat);
    cudaGetSymbolAddress((void**)&pq, g_pq);
    cudaGetSymbolAddress((void**)&pk, g_pk);
    cudaGetSymbolAddress((void**)&wql, g_wql);
    cudaGetSymbolAddress((void**)&cql, g_cql);
    cudaGetSymbolAddress((void**)&u, g_u);
    cudaGetSymbolAddress((void**)&cv, g_cv);
    cudaGetSymbolAddress((void**)&hsh, g_hsh);
    cudaGetSymbolAddress((void**)&qh, g_qh);
    cudaGetSymbolAddress((void**)&wq, g_wq);
    cudaGetSymbolAddress((void**)&wk, g_wk);
    cudaGetSymbolAddress((void**)&wt, g_wt);
    cudaGetSymbolAddress((void**)&wtb, g_wtb);

    cudaFuncSetAttribute(qlogits_kernel,
                         cudaFuncAttributeMaxDynamicSharedMemorySize, 65536);
    cudaFuncSetAttribute(wql_kernel,
                         cudaFuncAttributeMaxDynamicSharedMemorySize, 65536);
    cudaFuncSetAttribute(qklogits_kernel,
                         cudaFuncAttributeMaxDynamicSharedMemorySize, 65536);
    cudaFuncSetAttribute(gemm_tc<0>,
                         cudaFuncAttributeMaxDynamicSharedMemorySize, SMEMB);
    cudaFuncSetAttribute(gemm_tc<1>,
                         cudaFuncAttributeMaxDynamicSharedMemorySize, SMEMB);

    const int conv_blocks = (MM * DD / 4) / 256;   // 16384
    dim3 wgrid(DD / 32, DD / 32);
    dim3 ggrid(DD / 128, MM / 128);                // (8, 128)
    dim3 pgrid(NCH, Bb);                           // (16, 8)
    dim3 sgrid(DD * DD / 1024, Bb);                // (1024, 8)

    // conversions + combined q-logit weight (independent of GEMMs)
    conv_half<<<conv_blocks, 256>>>(hs, hsh);
    conv_w<<<wgrid, 256>>>(Wq, wq);
    conv_w<<<wgrid, 256>>>(Wk, wk);
    conv_w<<<wgrid, 256>>>(Wt, wt);
    wql_kernel<<<64, 256, 65536>>>(Wq, Wqa, bq, bqa, wql, cql);

    // qh = fp16(hs @ Wq + bq)
    gemm_tc<0><<<ggrid, 256, SMEMB>>>(hsh, wq, bq, nullptr, nullptr, qh, 0);

    // pooled_q path (entirely from hs)
    qlogits_kernel<<<MM / 32, 256, 65536>>>(wql, cql, hs, qlt);
    poolpart_kernel<<<pgrid, 256>>>(qlt, mask, hs, ypart, mstat);
    poolproj_kernel<<<Bb * HH, 256>>>(ypart, mstat, wq, bq, pq);

    // pooled_k path (entirely from hs; k never materialized)
    uvec_kernel<<<Bb * HH, 256>>>(Wk, bk, pq, u, cv);
    qklogits_kernel<<<pgrid, 256, 65536>>>(hs, u, cv, qkl);
    poolpart_kernel<<<pgrid, 256>>>(qkl, mask, hs, ypart, mstat);
    poolproj_kernel<<<Bb * HH, 256>>>(ypart, mstat, wk, bk, pk);

    // per-batch scaled transform weight, then final GEMM with residual
    scale_wt_kernel<<<sgrid, 256>>>(wt, pk, wtb);
    gemm_tc<1><<<ggrid, 256, SMEMB>>>(qh, wtb, bt, qh, out, nullptr, DD * DD);
}

// round 15
// speedup vs baseline: 1.1975x; 1.1975x over previous
#include <cuda_runtime.h>
#include <cuda_fp16.h>
#include <cstdint>
#include <math.h>

#define Bb 8
#define SS 2048
#define DD 1024
#define HH 16
#define DHH 64
#define MM (Bb * SS)
#define SCALE 0.125f
#define NCH 8               // S-chunks for pooling kernels
#define CHS (SS / NCH)      // 256

// ---------------- helpers ---------------------------------------------------
__device__ __forceinline__ uint32_t smem_to_u32(const void* p) {
    uint32_t a;
    asm("{ .reg .u64 t; cvta.to.shared.u64 t, %1; cvt.u32.u64 %0, t; }"
        : "=r"(a) : "l"(p));
    return a;
}
__device__ __forceinline__ void ldsm_x4(uint32_t* r, uint32_t addr) {
    asm volatile("ldmatrix.sync.aligned.m8n8.x4.shared.b16 {%0,%1,%2,%3}, [%4];"
        : "=r"(r[0]), "=r"(r[1]), "=r"(r[2]), "=r"(r[3]) : "r"(addr));
}
__device__ __forceinline__ void mma16816(float* c, const uint32_t* a,
                                         uint32_t b0, uint32_t b1) {
    asm volatile("mma.sync.aligned.m16n8k16.row.col.f32.f16.f16.f32 "
        "{%0,%1,%2,%3}, {%4,%5,%6,%7}, {%8,%9}, {%0,%1,%2,%3};"
        : "+f"(c[0]), "+f"(c[1]), "+f"(c[2]), "+f"(c[3])
        : "r"(a[0]), "r"(a[1]), "r"(a[2]), "r"(a[3]), "r"(b0), "r"(b1));
}
__device__ __forceinline__ void cp_async16(uint32_t saddr, const void* gaddr) {
    asm volatile("cp.async.cg.shared.global [%0], [%1], 16;"
        :: "r"(saddr), "l"(gaddr));
}
#define CP_COMMIT() asm volatile("cp.async.commit_group;" ::: "memory")
#define CP_WAIT_1() asm volatile("cp.async.wait_group 1;" ::: "memory")
#define CP_WAIT_0() asm volatile("cp.async.wait_group 0;" ::: "memory")

// ---------------- scratch (device globals) ---------------------------------
__device__ float g_q[(size_t)MM * DD];
__device__ float g_k[(size_t)MM * DD];
__device__ float g_qlt[Bb * HH * SS];           // q logits, [bh][s]
__device__ float g_part[Bb * HH * NCH * DHH];   // q-path pool partials
__device__ float g_mstat[Bb * HH * NCH * 2];    // q-path (max, expsum)
__device__ float g_part2[Bb * HH * NCH * DHH];  // k-path pool partials
__device__ float g_mstat2[Bb * HH * NCH * 2];   // k-path (max, expsum)
__device__ float g_pk[Bb * HH * DHH];
__device__ __half g_hsh[(size_t)MM * DD];
__device__ __half g_qh[(size_t)MM * DD];        // fp16 q (GEMM1 epi)
__device__ __half g_wq[DD * DD];
__device__ __half g_wk[DD * DD];
__device__ __half g_wt[DD * DD];
__device__ __half g_wtb[(size_t)Bb * DD * DD];  // per-batch pk-scaled Wt^T

// ---------------- conversion: fp32 -> fp16 ----------------------------------
__global__ void __launch_bounds__(256)
conv_half(const float* __restrict__ X, __half* __restrict__ out)
{
    size_t e = (size_t)blockIdx.x * 256 + threadIdx.x;  // float4 index
    float4 v = ((const float4*)X)[e];
    __half hv[4];
    hv[0] = __float2half_rn(v.x); hv[1] = __float2half_rn(v.y);
    hv[2] = __float2half_rn(v.z); hv[3] = __float2half_rn(v.w);
    ((uint2*)out)[e] = *(uint2*)hv;
}

// ---------------- conversion: weight transpose to fp16 ---------------------
__global__ void __launch_bounds__(256)
conv_w(const float* __restrict__ W, __half* __restrict__ wt)
{
    __shared__ float s[32][33];
    int n0 = blockIdx.x * 32, k0 = blockIdx.y * 32;
    int tx = threadIdx.x & 31, ty = threadIdx.x >> 5;  // 32 x 8
#pragma unroll
    for (int i = 0; i < 4; i++) {
        int r = ty + i * 8;
        s[r][tx] = W[(size_t)(k0 + r) * DD + n0 + tx];
    }
    __syncthreads();
#pragma unroll
    for (int i = 0; i < 4; i++) {
        int r = ty + i * 8;
        wt[(size_t)(n0 + r) * DD + k0 + tx] = __float2half_rn(s[tx][r]);
    }
}

// ---------------- per-batch scaled weight: W'_b[n][k] = wt[n][k]*pk[b][k] --
__global__ void __launch_bounds__(256)
scale_wt_kernel(const __half* __restrict__ wt, const float* __restrict__ pk,
                __half* __restrict__ wtb)
{
    int b = blockIdx.y;
    size_t e = (size_t)blockIdx.x * 1024 + threadIdx.x * 4;  // half index
    int kk = (int)(e & (DD - 1));
    uint2 raw = *(const uint2*)(wt + e);
    __half* hv = (__half*)&raw;
    float4 p = *(const float4*)(pk + (size_t)b * DD + kk);
    __half ov[4];
    ov[0] = __float2half_rn(__half2float(hv[0]) * p.x);
    ov[1] = __float2half_rn(__half2float(hv[1]) * p.y);
    ov[2] = __float2half_rn(__half2float(hv[2]) * p.z);
    ov[3] = __float2half_rn(__half2float(hv[3]) * p.w);
    *(uint2*)(wtb + (size_t)b * DD * DD + e) = *(uint2*)ov;
}

// ---------------- shared GEMM constants ------------------------------------
constexpr int PITCH = 80;                  // bytes per 32-elem fp16 row
constexpr int TILEB = 128 * PITCH;         // 10240
constexpr int STAGEB = 2 * TILEB;          // 20480
constexpr int SMEMB = 3 * STAGEB;          // 61440
constexpr int NKT = 32;

// ---------------- fused q/k projection GEMM (grid.z = 2) -------------------
// z=0: q = hs@Wq^T + bq  (fp32 + fp16 copy);  z=1: k = hs@Wk^T + bk (fp32)
__global__ void __launch_bounds__(256, 2)
gemm_qk(const __half* __restrict__ Ah,
        const __half* __restrict__ Bw0, const __half* __restrict__ Bw1,
        const float* __restrict__ bias0, const float* __restrict__ bias1,
        float* __restrict__ C0, float* __restrict__ C1,
        __half* __restrict__ Ch0)
{
    extern __shared__ char smem[];
    const uint32_t sb = smem_to_u32(smem);
    const int tid = threadIdx.x, wid = tid >> 5, lane = tid & 31;
    const int warp_m = wid & 3, warp_n = wid >> 2;
    const int n0 = blockIdx.x * 128;
    const int m0 = blockIdx.y * 128;
    const int z = blockIdx.z;
    const __half* Bw = z ? Bw1 : Bw0;
    const float* bias = z ? bias1 : bias0;
    float* C = z ? C1 : C0;

    float acc[2][8][4];
#pragma unroll
    for (int i = 0; i < 2; i++)
#pragma unroll
        for (int j = 0; j < 8; j++)
#pragma unroll
            for (int l = 0; l < 4; l++) acc[i][j][l] = 0.0f;

    auto load_stage = [&](int kt, int st) {
        const int k0 = kt * 32;
#pragma unroll
        for (int tile = 0; tile < 2; tile++) {
            const int rowoff = (tile == 0) ? m0 : n0;
            const __half* base = (tile == 0) ? Ah : Bw;
#pragma unroll
            for (int h = 0; h < 2; h++) {
                int c = tid + h * 256;
                int row = c >> 2, cc = c & 3;
                uint32_t sa = sb + st * STAGEB + tile * TILEB + row * PITCH + cc * 16;
                cp_async16(sa, base + (size_t)(rowoff + row) * DD + k0 + cc * 8);
            }
        }
    };

    load_stage(0, 0); CP_COMMIT();
    load_stage(1, 1); CP_COMMIT();

    for (int kt = 0; kt < NKT; kt++) {
        if (kt == NKT - 1) { CP_WAIT_0(); } else { CP_WAIT_1(); }
        __syncthreads();
        if (kt + 2 < NKT) {
            load_stage(kt + 2, (kt + 2) % 3);
            CP_COMMIT();
        }

        const uint32_t s0 = sb + (kt % 3) * STAGEB;
        const int rsel = lane & 15;
        const int hsel = (lane >> 4) * 16;

#pragma unroll
        for (int kp = 0; kp < 2; kp++) {
            uint32_t ah[2][4];
            const int ksel = hsel + kp * 32;
#pragma unroll
            for (int mi = 0; mi < 2; mi++) {
                uint32_t off = (uint32_t)(warp_m * 32 + mi * 16 + rsel) * PITCH + ksel;
                ldsm_x4(ah[mi], s0 + off);
            }
#pragma unroll
            for (int np = 0; np < 4; np++) {
                uint32_t off = (uint32_t)(warp_n * 64 + np * 16 + rsel) * PITCH + ksel;
                uint32_t bh[4];
                ldsm_x4(bh, s0 + TILEB + off);
#pragma unroll
                for (int mi = 0; mi < 2; mi++) {
                    mma16816(acc[mi][2 * np],     ah[mi], bh[0], bh[2]);
                    mma16816(acc[mi][2 * np + 1], ah[mi], bh[1], bh[3]);
                }
            }
        }
    }

#pragma unroll
    for (int mi = 0; mi < 2; mi++) {
        int row = m0 + warp_m * 32 + mi * 16 + (lane >> 2);
#pragma unroll
        for (int ni = 0; ni < 8; ni++) {
            int col = n0 + warp_n * 64 + ni * 8 + (lane & 3) * 2;
            float b0 = __ldg(bias + col), b1 = __ldg(bias + col + 1);
            float2 v0, v1;
            v0.x = acc[mi][ni][0] + b0;  v0.y = acc[mi][ni][1] + b1;
            v1.x = acc[mi][ni][2] + b0;  v1.y = acc[mi][ni][3] + b1;
            *(float2*)(C + (size_t)row * DD + col) = v0;
            *(float2*)(C + (size_t)(row + 8) * DD + col) = v1;
            if (z == 0) {
                *(__half2*)(Ch0 + (size_t)row * DD + col) =
                    __floats2half2_rn(v0.x, v0.y);
                *(__half2*)(Ch0 + (size_t)(row + 8) * DD + col) =
                    __floats2half2_rn(v1.x, v1.y);
            }
        }
    }
}

// ---------------- final transform GEMM: out = qh @ W'_b + bt + q -----------
__global__ void __launch_bounds__(256, 2)
gemm_final(const __half* __restrict__ Ah, const __half* __restrict__ Bw,
           const float* __restrict__ bias, const float* __restrict__ resid,
           float* __restrict__ C, int bStrideBatch)
{
    extern __shared__ char smem[];
    const uint32_t sb = smem_to_u32(smem);
    const int tid = threadIdx.x, wid = tid >> 5, lane = tid & 31;
    const int warp_m = wid & 3, warp_n = wid >> 2;
    const int n0 = blockIdx.x * 128;
    const int m0 = blockIdx.y * 128;
    Bw += (size_t)(m0 >> 11) * bStrideBatch;

    float acc[2][8][4];
#pragma unroll
    for (int i = 0; i < 2; i++)
#pragma unroll
        for (int j = 0; j < 8; j++)
#pragma unroll
            for (int l = 0; l < 4; l++) acc[i][j][l] = 0.0f;

    auto load_stage = [&](int kt, int st) {
        const int k0 = kt * 32;
#pragma unroll
        for (int tile = 0; tile < 2; tile++) {
            const int rowoff = (tile == 0) ? m0 : n0;
            const __half* base = (tile == 0) ? Ah : Bw;
#pragma unroll
            for (int h = 0; h < 2; h++) {
                int c = tid + h * 256;
                int row = c >> 2, cc = c & 3;
                uint32_t sa = sb + st * STAGEB + tile * TILEB + row * PITCH + cc * 16;
                cp_async16(sa, base + (size_t)(rowoff + row) * DD + k0 + cc * 8);
            }
        }
    };

    load_stage(0, 0); CP_COMMIT();
    load_stage(1, 1); CP_COMMIT();

    for (int kt = 0; kt < NKT; kt++) {
        if (kt == NKT - 1) { CP_WAIT_0(); } else { CP_WAIT_1(); }
        __syncthreads();
        if (kt + 2 < NKT) {
            load_stage(kt + 2, (kt + 2) % 3);
            CP_COMMIT();
        }

        const uint32_t s0 = sb + (kt % 3) * STAGEB;
        const int rsel = lane & 15;
        const int hsel = (lane >> 4) * 16;

#pragma unroll
        for (int kp = 0; kp < 2; kp++) {
            uint32_t ah[2][4];
            const int ksel = hsel + kp * 32;
#pragma unroll
            for (int mi = 0; mi < 2; mi++) {
                uint32_t off = (uint32_t)(warp_m * 32 + mi * 16 + rsel) * PITCH + ksel;
                ldsm_x4(ah[mi], s0 + off);
            }
#pragma unroll
            for (int np = 0; np < 4; np++) {
                uint32_t off = (uint32_t)(warp_n * 64 + np * 16 + rsel) * PITCH + ksel;
                uint32_t bh[4];
                ldsm_x4(bh, s0 + TILEB + off);
#pragma unroll
                for (int mi = 0; mi < 2; mi++) {
                    mma16816(acc[mi][2 * np],     ah[mi], bh[0], bh[2]);
                    mma16816(acc[mi][2 * np + 1], ah[mi], bh[1], bh[3]);
                }
            }
        }
    }

#pragma unroll
    for (int mi = 0; mi < 2; mi++) {
        int row = m0 + warp_m * 32 + mi * 16 + (lane >> 2);
#pragma unroll
        for (int ni = 0; ni < 8; ni++) {
            int col = n0 + warp_n * 64 + ni * 8 + (lane & 3) * 2;
            float b0 = __ldg(bias + col), b1 = __ldg(bias + col + 1);
            float2 v0, v1;
            v0.x = acc[mi][ni][0] + b0;  v0.y = acc[mi][ni][1] + b1;
            v1.x = acc[mi][ni][2] + b0;  v1.y = acc[mi][ni][3] + b1;
            float2 r0 = *(const float2*)(resid + (size_t)row * DD + col);
            float2 r1 = *(const float2*)(resid + (size_t)(row + 8) * DD + col);
            v0.x += r0.x; v0.y += r0.y; v1.x += r1.x; v1.y += r1.y;
            *(float2*)(C + (size_t)row * DD + col) = v0;
            *(float2*)(C + (size_t)(row + 8) * DD + col) = v1;
        }
    }
}

// ---------------- q attention logits (vectorized, output [bh][s]) ----------
__global__ void __launch_bounds__(256)
qlogits_kernel(const float* __restrict__ Wqa, const float* __restrict__ bqa,
               const float* __restrict__ q, float* __restrict__ qlt)
{
    extern __shared__ float sW[];   // [HH][DD] transposed, 64 KB
    int tid = threadIdx.x;
    for (int i = tid; i < DD * HH; i += 256) {
        int k = i >> 4, h = i & 15;
        sW[h * DD + k] = Wqa[i];
    }
    __syncthreads();

    int warp = tid >> 5, lane = tid & 31;
    for (int rr = 0; rr < 4; rr++) {
        int m = blockIdx.x * 32 + warp * 4 + rr;
        const float4* qrow4 = (const float4*)(q + (size_t)m * DD);
        float acc[HH];
#pragma unroll
        for (int h = 0; h < HH; h++) acc[h] = 0.0f;
#pragma unroll
        for (int it = 0; it < 8; it++) {
            float4 qv = qrow4[lane + 32 * it];
            int k4 = (lane + 32 * it) * 4;
#pragma unroll
            for (int h = 0; h < HH; h++) {
                float4 w = *(const float4*)(sW + h * DD + k4);
                acc[h] += qv.x * w.x + qv.y * w.y + qv.z * w.z + qv.w * w.w;
            }
        }
#pragma unroll
        for (int h = 0; h < HH; h++)
#pragma unroll
            for (int off = 16; off; off >>= 1)
                acc[h] += __shfl_xor_sync(0xffffffffu, acc[h], off);
        if (lane == 0) {
            int b = m >> 11, s = m & (SS - 1);
#pragma unroll
            for (int h = 0; h < HH; h++)
                qlt[((size_t)(b * HH + h)) * SS + s] = acc[h] + bqa[h];
        }
    }
}

// ---------------- pool partial with LOCAL softmax stats (q path) -----------
__global__ void __launch_bounds__(256)
poolpart_kernel(const float* __restrict__ lt, const float* __restrict__ mask,
                const float* __restrict__ src, float* __restrict__ part,
                float* __restrict__ mstat)
{
    __shared__ float w[CHS];
    __shared__ float red[256];
    int ch = blockIdx.x, bh = blockIdx.y;
    int b = bh >> 4, h = bh & 15;
    int s0 = ch * CHS;
    int t = threadIdx.x;

    float l = lt[(size_t)bh * SS + s0 + t] * SCALE + mask[(size_t)b * SS + s0 + t];
    red[t] = l; __syncthreads();
    for (int off = 128; off; off >>= 1) {
        if (t < off) red[t] = fmaxf(red[t], red[t + off]);
        __syncthreads();
    }
    float mloc = red[0];
    __syncthreads();

    float e = __expf(l - mloc);
    w[t] = e;
    red[t] = e; __syncthreads();
    for (int off = 128; off; off >>= 1) {
        if (t < off) red[t] += red[t + off];
        __syncthreads();
    }
    float esum = red[0];
    __syncthreads();

    int dh = t & 63, sg = t >> 6;          // 4 s-groups x 64 dh
    const float* src2 = src + ((size_t)(b * SS + s0 + sg)) * DD + h * DHH + dh;
    float acc = 0.0f;
#pragma unroll 16
    for (int i = 0; i < CHS / 4; i++)
        acc += w[sg + 4 * i] * src2[(size_t)4 * i * DD];
    red[t] = acc; __syncthreads();
    if (t < 64)
        part[((size_t)bh * NCH + ch) * DHH + t] =
            red[t] + red[t + 64] + red[t + 128] + red[t + 192];
    if (t == 0) {
        mstat[((size_t)bh * NCH + ch) * 2]     = mloc;
        mstat[((size_t)bh * NCH + ch) * 2 + 1] = esum;
    }
}

// ---------------- fused pq-reduce + qk logits + pool partial (k path) ------
__global__ void __launch_bounds__(256)
qk_pool_kernel(const float* __restrict__ kx,
               const float* __restrict__ partq, const float* __restrict__ mstatq,
               const float* __restrict__ mask,
               float* __restrict__ partk, float* __restrict__ mstatk)
{
    __shared__ float w[CHS];
    __shared__ float red[256];
    __shared__ float spq[DHH];
    int ch = blockIdx.x, bh = blockIdx.y;
    int b = bh >> 4, h = bh & 15;
    int s0 = ch * CHS;
    int t = threadIdx.x;

    // inline reduction of q-path partials -> pq (replaces poolred launch)
    if (t < DHH) {
        float ml[NCH], es[NCH];
        float gmax = -1e30f;
#pragma unroll
        for (int c = 0; c < NCH; c++) {
            ml[c] = mstatq[((size_t)bh * NCH + c) * 2];
            es[c] = mstatq[((size_t)bh * NCH + c) * 2 + 1];
            gmax = fmaxf(gmax, ml[c]);
        }
        float denom = 0.0f, a = 0.0f;
#pragma unroll
        for (int c = 0; c < NCH; c++) {
            float f = __expf(ml[c] - gmax);
            denom += es[c] * f;
            a += partq[((size_t)bh * NCH + c) * DHH + t] * f;
        }
        spq[t] = a / denom;
    }
    __syncthreads();

    int warp = t >> 5, lane = t & 31;
    float p0 = spq[lane], p1 = spq[lane + 32];
    const float* kb = kx + ((size_t)b * SS) * DD + h * DHH;
#pragma unroll 4
    for (int i = 0; i < 32; i++) {
        int sl = warp * 32 + i;
        const float* kr = kb + (size_t)(s0 + sl) * DD;
        float prt = kr[lane] * p0 + kr[lane + 32] * p1;
#pragma unroll
        for (int off = 16; off; off >>= 1)
            prt += __shfl_xor_sync(0xffffffffu, prt, off);
        if (lane == 0)
            w[sl] = prt * SCALE + mask[(size_t)b * SS + s0 + sl];
    }
    __syncthreads();

    float l = w[t];
    red[t] = l; __syncthreads();
    for (int off = 128; off; off >>= 1) {
        if (t < off) red[t] = fmaxf(red[t], red[t + off]);
        __syncthreads();
    }
    float mloc = red[0];
    __syncthreads();

    float e = __expf(l - mloc);
    w[t] = e;
    red[t] = e; __syncthreads();
    for (int off = 128; off; off >>= 1) {
        if (t < off) red[t] += red[t + off];
        __syncthreads();
    }
    float esum = red[0];
    __syncthreads();

    int dh = t & 63, sg = t >> 6;
    const float* src2 = kb + (size_t)(s0 + sg) * DD + dh;
    float acc = 0.0f;
#pragma unroll 16
    for (int i = 0; i < CHS / 4; i++)
        acc += w[sg + 4 * i] * src2[(size_t)4 * i * DD];
    red[t] = acc; __syncthreads();
    if (t < 64)
        partk[((size_t)bh * NCH + ch) * DHH + t] =
            red[t] + red[t + 64] + red[t + 128] + red[t + 192];
    if (t == 0) {
        mstatk[((size_t)bh * NCH + ch) * 2]     = mloc;
        mstatk[((size_t)bh * NCH + ch) * 2 + 1] = esum;
    }
}

// ---------------- reduce partials with global rescale (k path) --------------
__global__ void __launch_bounds__(64)
poolred_kernel(const float* __restrict__ part, const float* __restrict__ mstat,
               float* __restrict__ out)
{
    int bh = blockIdx.x, t = threadIdx.x;
    float ml[NCH], ss[NCH];
    float gmax = -1e30f;
#pragma unroll
    for (int c = 0; c < NCH; c++) {
        ml[c] = mstat[((size_t)bh * NCH + c) * 2];
        ss[c] = mstat[((size_t)bh * NCH + c) * 2 + 1];
        gmax = fmaxf(gmax, ml[c]);
    }
    float denom = 0.0f, acc = 0.0f;
#pragma unroll
    for (int c = 0; c < NCH; c++) {
        float f = __expf(ml[c] - gmax);
        denom += ss[c] * f;
        acc += part[((size_t)bh * NCH + c) * DHH + t] * f;
    }
    out[(size_t)bh * DHH + t] = acc / denom;
}

// ---------------------------------------------------------------------------
extern "C" void kernel_launch(void* const* d_in, const int* in_sizes, int n_in,
                              void* d_out, int out_size)
{
    const float* hs   = (const float*)d_in[0];
    const float* mask = (const float*)d_in[1];
    const float* Wq   = (const float*)d_in[2];
    const float* bq   = (const float*)d_in[3];
    const float* Wqa  = (const float*)d_in[4];
    const float* bqa  = (const float*)d_in[5];
    const float* Wk   = (const float*)d_in[6];
    const float* bk   = (const float*)d_in[7];
    const float* Wt   = (const float*)d_in[8];
    const float* bt   = (const float*)d_in[9];
    float* out = (float*)d_out;

    float *q, *k, *qlt, *partp, *mstat, *partp2, *mstat2, *pk;
    __half *hsh, *qh, *wq, *wk, *wt, *wtb;
    cudaGetSymbolAddress((void**)&q,  g_q);
    cudaGetSymbolAddress((void**)&k,  g_k);
    cudaGetSymbolAddress((void**)&qlt, g_qlt);
    cudaGetSymbolAddress((void**)&partp, g_part);
    cudaGetSymbolAddress((void**)&mstat, g_mstat);
    cudaGetSymbolAddress((void**)&partp2, g_part2);
    cudaGetSymbolAddress((void**)&mstat2, g_mstat2);
    cudaGetSymbolAddress((void**)&pk, g_pk);
    cudaGetSymbolAddress((void**)&hsh, g_hsh);
    cudaGetSymbolAddress((void**)&qh, g_qh);
    cudaGetSymbolAddress((void**)&wq, g_wq);
    cudaGetSymbolAddress((void**)&wk, g_wk);
    cudaGetSymbolAddress((void**)&wt, g_wt);
    cudaGetSymbolAddress((void**)&wtb, g_wtb);

    cudaFuncSetAttribute(qlogits_kernel,
                         cudaFuncAttributeMaxDynamicSharedMemorySize, 65536);
    cudaFuncSetAttribute(gemm_qk,
                         cudaFuncAttributeMaxDynamicSharedMemorySize, SMEMB);
    cudaFuncSetAttribute(gemm_final,
                         cudaFuncAttributeMaxDynamicSharedMemorySize, SMEMB);

    const int conv_blocks = (MM * DD / 4) / 256;   // 16384
    dim3 wgrid(DD / 32, DD / 32);
    dim3 qkgrid(DD / 128, MM / 128, 2);            // (8, 128, 2)
    dim3 ggrid(DD / 128, MM / 128);                // (8, 128)
    dim3 pgrid(NCH, Bb * HH);                      // (8, 128)
    dim3 sgrid(DD * DD / 1024, Bb);                // (1024, 8)

    // conversions
    conv_half<<<conv_blocks, 256>>>(hs, hsh);
    conv_w<<<wgrid, 256>>>(Wq, wq);
    conv_w<<<wgrid, 256>>>(Wk, wk);
    conv_w<<<wgrid, 256>>>(Wt, wt);

    // fused: q = hs@Wq + bq (+fp16 copy) ; k = hs@Wk + bk
    gemm_qk<<<qkgrid, 256, SMEMB>>>(hsh, wq, wk, bq, bk, q, k, qh);

    // pooled_q partials
    qlogits_kernel<<<MM / 32, 256, 65536>>>(Wqa, bqa, q, qlt);
    poolpart_kernel<<<pgrid, 256>>>(qlt, mask, q, partp, mstat);

    // pooled_k path (inline pq reduce + fused logits + pool)
    qk_pool_kernel<<<pgrid, 256>>>(k, partp, mstat, mask, partp2, mstat2);
    poolred_kernel<<<Bb * HH, 64>>>(partp2, mstat2, pk);

    // per-batch scaled transform weight, then final GEMM with residual
    scale_wt_kernel<<<sgrid, 256>>>(wt, pk, wtb);
    gemm_final<<<ggrid, 256, SMEMB>>>(qh, wtb, bt, q, out, DD * DD);
}